// round 13
// baseline (speedup 1.0000x reference)
#include <cuda_runtime.h>
#include <cstddef>

#define G_CELLS 8000
#define T_STEPS 730
#define CH 10              // steps per chunk; 730 = 10 * 73
#define NCHUNK 73
#define CPB 64             // cells per block; 8000 = 125 * 64
#define NEARZERO_F 1e-5f

__device__ __forceinline__ float ex2f_(float x) {
    float r; asm("ex2.approx.f32 %0, %1;" : "=f"(r) : "f"(x)); return r;
}
__device__ __forceinline__ float lg2f_(float x) {
    float r; asm("lg2.approx.f32 %0, %1;" : "=f"(r) : "f"(x)); return r;
}

// Named barriers at SUPER-CHUNK (2-chunk) granularity, 4-slot data ring.
// full: id 1+(j&1) (producer -> consumer), free: id 3+(j&1) (consumer -> producer).
// count = 128 (2 consumer warps + 2 producer warps). bar.sync/arrive carry
// membar.cta-equivalent fence semantics.
#define BAR_SYNC(id)   asm volatile("bar.sync %0, 128;"   :: "r"(id) : "memory")
#define BAR_ARRIVE(id) asm volatile("bar.arrive %0, 128;" :: "r"(id) : "memory")

__global__ __launch_bounds__(256, 1) void hbv_kernel(
    const float* __restrict__ xphy,    // [730, 8000, 3] (P, T, PET)
    const float* __restrict__ params,  // [730, 8000, 14]
    float* __restrict__ out)           // [730, 8000]
{
    __shared__ float2 buf[4][CH][CPB];   // (inflow, PET) producer -> consumer
    __shared__ float  qbuf[4][CH][CPB];  // Q results    consumer -> producer

    const int tid  = threadIdx.x;
    const int wid  = tid >> 5;
    const int lane = tid & 31;

    // SMSP = wid % 4.  Consumers: wid 0 & 4 -> BOTH on SMSP 0 (SMT overlap:
    // each warp's chain-stall holes absorb the other's issue).  Producers:
    // wid 1 -> SMSP 1, wid 2 -> SMSP 2.  Other warps exit.
    const bool is_consumer = (wid == 0) || (wid == 4);
    const bool is_producer = (wid == 1) || (wid == 2);
    if (!is_consumer && !is_producer) return;

    const int half  = is_consumer ? (wid == 4 ? 1 : 0) : (wid == 2 ? 1 : 0);
    const int cslot = half * 32 + lane;          // cell slot within block
    const int g = blockIdx.x * CPB + cslot;      // always < 8000

    // BETA, FC, K0, K1, K2, LP, PERCmax, UZL, TT, CFMAX, CFR, CWH, BETAET, C
    const float lo[14] = {1.0f, 50.0f, 0.05f, 0.01f, 0.001f, 0.2f, 0.0f,
                          0.0f, -2.5f, 0.5f, 0.0f, 0.0f, 0.3f, 0.0f};
    const float hi[14] = {6.0f, 1000.0f, 0.9f, 0.5f, 0.2f, 1.0f, 10.0f,
                          100.0f, 2.5f, 10.0f, 0.1f, 0.2f, 5.0f, 1.0f};

    const float* pr = params + ((size_t)(T_STEPS - 1) * G_CELLS + (size_t)g) * 14;
    float phy[14];
#pragma unroll
    for (int i = 0; i < 14; i++) {
        const float s = 1.0f / (1.0f + __expf(-pr[i]));
        phy[i] = fmaf(s, hi[i] - lo[i], lo[i]);
    }

    if (is_producer) {
        // -------- PRODUCER: snow recurrence + input loads + Q store-out --------
        const float TT = phy[8], CFMAX = phy[9], CWH = phy[11];
        const float CFRCF = phy[10] * phy[9];

        float SP = 0.001f, MW = 0.001f;

        auto snow_adv = [&](float P, float Tm) -> float {
            const bool  rain = (Tm >= TT);
            const float RAIN = rain ? P : 0.0f;
            const float SNOW = rain ? 0.0f : P;
            const float w    = (rain ? CFMAX : CFRCF) * (Tm - TT);
            const float SP1  = SP + SNOW;
            const float transfer = fminf(fmaxf(w, -MW), SP1);
            SP = SP1 - transfer;
            const float MW2 = MW + transfer;
            const float v   = fmaf(-CWH, SP, MW2);
            const float tosoil = fmaxf(v, 0.0f);
            MW = MW2 - tosoil;
            return RAIN + tosoil;
        };

        auto flush_q = [&](int m) {
            float* o = out + (size_t)(m * CH) * G_CELLS + g;
            const int s = m & 3;
#pragma unroll
            for (int i = 0; i < CH; i++) {
                o[(size_t)i * G_CELLS] = qbuf[s][i][cslot];
            }
        };

        // Raw-input ring: next chunk's inputs, loaded one chunk early.
        float rP[CH], rT[CH], rE[CH];
        const float* xp = xphy + (size_t)g * 3;     // step 0
#pragma unroll
        for (int i = 0; i < CH; i++) {
            rP[i] = xp[0]; rT[i] = xp[1]; rE[i] = xp[2];
            xp += (size_t)G_CELLS * 3;
        }
        for (int k = 0; k < NCHUNK - 1; ++k) {       // chunks 0..71
            if (((k & 1) == 0) && k >= 4) {
                BAR_SYNC(3 + ((k >> 1) & 1));        // consumer freed super (k/2-2)
                flush_q(k - 4);
                flush_q(k - 3);
            }
            const int s = k & 3;
#pragma unroll
            for (int i = 0; i < CH; i++) {
                const float P = rP[i], Tm = rT[i], PE = rE[i];
                rP[i] = xp[0]; rT[i] = xp[1]; rE[i] = xp[2];
                xp += (size_t)G_CELLS * 3;
                const float inflow = snow_adv(P, Tm);
                buf[s][i][cslot] = make_float2(inflow, PE);
            }
            if (k & 1) BAR_ARRIVE(1 + ((k >> 1) & 1));   // super-chunk full
        }
        {   // final chunk 72 (slot 0): no loads
            BAR_SYNC(3);                              // consumer freed super 34
            flush_q(68);
            flush_q(69);
#pragma unroll
            for (int i = 0; i < CH; i++) {
                const float inflow = snow_adv(rP[i], rT[i]);
                buf[0][i][cslot] = make_float2(inflow, rE[i]);
            }
            BAR_ARRIVE(1);                            // "super 36" full
        }
        // Tail flushes as consumer finishes.
        BAR_SYNC(4);   // super 35 freed
        flush_q(70);
        flush_q(71);
        BAR_SYNC(3);   // super 36 (chunk 72) freed
        flush_q(72);
    } else {
        // -------- CONSUMER: SM/SUZ/SLZ chain (rotated: lgSM carried) --------
        const float BETA = phy[0], FC = phy[1], K0 = phy[2], K1 = phy[3];
        const float K2 = phy[4], LP = phy[5], PERCmax = phy[6], UZL = phy[7];
        const float BETAET = phy[12], C = phy[13];

        const float invFC = 1.0f / FC;
        const float clgA  = BETA   * lg2f_(invFC);
        const float clgB  = BETAET * lg2f_(1.0f / (LP * FC));
        const float oneK0 = 1.0f - K0;
        const float K0UZL = K0 * UZL;
        const float oneK1 = 1.0f - K1;

        float SM = 0.001f, SUZ = 0.001f, SLZ = 0.001f;
        float CSLZ = C * SLZ;
        float omcf = 1.0f - CSLZ * invFC;
        float lgSM = lg2f_(SM);                 // rotated loop-carried value

        auto do_chunk = [&](int k) {
            const int s = k & 3;
            float2 v[CH];
#pragma unroll
            for (int i = 0; i < CH; i++) v[i] = buf[s][i][cslot];

#pragma unroll
            for (int i = 0; i < CH; i++) {
                const float inflow = v[i].x, PETt = v[i].y;

                // --- chain head (lgSM already computed last step) ---
                const float s1 = fminf(fmaf(BETA, lgSM, clgA), 0.0f);
                const float e1 = ex2f_(s1);
                // off-path in e1 shadow:
                const float t1 = SM + inflow;

                const float SM1 = fmaf(-inflow, e1, t1);   // >= SM
                const float lg1 = lg2f_(SM1);
                // off-path in lg1 shadow:
                const float SM2 = fminf(SM1, FC);
                const float floor3 = fmaxf(SM2 - PETt, NEARZERO_F);
                const float d = t1 - SM2;                  // recharge + excess

                const float e2 = ex2f_(fmaf(BETAET, lg1, clgB));
                // off-path in e2 shadow (SUZ front half):
                const float SUZ1 = SUZ + d;
                const float PERC = fminf(SUZ1, PERCmax);
                const float SUZ2 = fmaxf(SUZ1 - PERCmax, 0.0f);
                const float SUZ3 = fminf(SUZ2, fmaf(oneK0, SUZ2, K0UZL));
                SUZ = oneK1 * SUZ3;
                const float Q01 = SUZ2 - SUZ;

                // --- chain tail ---
                const float SM3 = fmaxf(fmaf(-PETt, e2, SM2), floor3);
                const float SMn = fmaf(omcf, SM3, CSLZ);   // + capillary
                SM = SMn;
                lgSM = lg2f_(SMn);             // ROTATED: next step's lg2 now
                // off-path tail in lgSM shadow:
                const float cap = SMn - SM3;
                const float SLZ1 = fmaxf(SLZ - cap, NEARZERO_F) + PERC;
                const float Q2 = K2 * SLZ1;
                SLZ = SLZ1 - Q2;
                CSLZ = C * SLZ;
                omcf = fmaf(-CSLZ, invFC, 1.0f);
                qbuf[s][i][cslot] = Q01 + Q2;
            }
        };

        // 36 full super-chunks (chunks 0..71), then final chunk 72.
        for (int j = 0; j < 36; ++j) {
            BAR_SYNC(1 + (j & 1));              // super full (acquire)
            do_chunk(2 * j);
            do_chunk(2 * j + 1);
            BAR_ARRIVE(3 + (j & 1));            // super free + Q ready (release)
        }
        BAR_SYNC(1);                            // "super 36" full
        do_chunk(72);
        BAR_ARRIVE(3);
    }
}

extern "C" void kernel_launch(void* const* d_in, const int* in_sizes, int n_in,
                              void* d_out, int out_size) {
    const float* xphy   = (const float*)d_in[0];   // 730*8000*3
    const float* params = (const float*)d_in[1];   // 730*8000*14
    float* out = (float*)d_out;                    // 730*8000

    hbv_kernel<<<125, 256>>>(xphy, params, out);   // 125 * 64 cells = 8000
}

// round 14
// speedup vs baseline: 1.0545x; 1.0545x over previous
#include <cuda_runtime.h>
#include <cstddef>

#define G_CELLS 8000
#define T_STEPS 730
#define CH 10              // steps per chunk; 730 = 10 * 73
#define NCHUNK 73
#define CPB 64             // cells per block; 8000 = 125 * 64
#define NEARZERO_F 1e-5f

__device__ __forceinline__ float ex2f_(float x) {
    float r; asm("ex2.approx.f32 %0, %1;" : "=f"(r) : "f"(x)); return r;
}
__device__ __forceinline__ float lg2f_(float x) {
    float r; asm("lg2.approx.f32 %0, %1;" : "=f"(r) : "f"(x)); return r;
}

// Named barriers at SUPER-CHUNK (2-chunk) granularity, 4-slot data ring.
// full: id 1+(j&1) (producer -> consumer), free: id 3+(j&1) (consumer -> producer).
// count = 128. bar.sync/arrive carry membar.cta-equivalent fence semantics.
#define BAR_SYNC(id)   asm volatile("bar.sync %0, 128;"   :: "r"(id) : "memory")
#define BAR_ARRIVE(id) asm volatile("bar.arrive %0, 128;" :: "r"(id) : "memory")

__global__ __launch_bounds__(128, 1) void hbv_kernel(
    const float* __restrict__ xphy,    // [730, 8000, 3] (P, T, PET)
    const float* __restrict__ params,  // [730, 8000, 14]
    float* __restrict__ out)           // [730, 8000]
{
    __shared__ float2 buf[4][CH][CPB];   // (inflow, PET) producer -> consumer
    __shared__ float  qbuf[4][CH][CPB];  // Q results    consumer -> producer

    const int tid  = threadIdx.x;
    const int lane = tid & 63;                 // cell slot within block
    const bool is_producer = (tid >= 64);
    const int g = blockIdx.x * CPB + lane;     // always < 8000

    // BETA, FC, K0, K1, K2, LP, PERCmax, UZL, TT, CFMAX, CFR, CWH, BETAET, C
    const float lo[14] = {1.0f, 50.0f, 0.05f, 0.01f, 0.001f, 0.2f, 0.0f,
                          0.0f, -2.5f, 0.5f, 0.0f, 0.0f, 0.3f, 0.0f};
    const float hi[14] = {6.0f, 1000.0f, 0.9f, 0.5f, 0.2f, 1.0f, 10.0f,
                          100.0f, 2.5f, 10.0f, 0.1f, 0.2f, 5.0f, 1.0f};

    const float* pr = params + ((size_t)(T_STEPS - 1) * G_CELLS + (size_t)g) * 14;
    float phy[14];
#pragma unroll
    for (int i = 0; i < 14; i++) {
        const float s = 1.0f / (1.0f + __expf(-pr[i]));
        phy[i] = fmaf(s, hi[i] - lo[i], lo[i]);
    }

    if (is_producer) {
        // -------- PRODUCER: snow recurrence + input loads + Q store-out --------
        const float TT = phy[8], CFMAX = phy[9], CWH = phy[11];
        const float CFRCF = phy[10] * phy[9];

        float SP = 0.001f, MW = 0.001f;

        auto snow_adv = [&](float P, float Tm) -> float {
            const bool  rain = (Tm >= TT);
            const float RAIN = rain ? P : 0.0f;
            const float SNOW = rain ? 0.0f : P;
            const float w    = (rain ? CFMAX : CFRCF) * (Tm - TT);
            const float SP1  = SP + SNOW;
            const float transfer = fminf(fmaxf(w, -MW), SP1);
            SP = SP1 - transfer;
            const float MW2 = MW + transfer;
            const float v   = fmaf(-CWH, SP, MW2);
            const float tosoil = fmaxf(v, 0.0f);
            MW = MW2 - tosoil;
            return RAIN + tosoil;
        };

        auto flush_q = [&](int m) {
            float* o = out + (size_t)(m * CH) * G_CELLS + g;
            const int s = m & 3;
#pragma unroll
            for (int i = 0; i < CH; i++) {
                o[(size_t)i * G_CELLS] = qbuf[s][i][lane];
            }
        };

        // Raw-input ring: next chunk's inputs, loaded one chunk early.
        float rP[CH], rT[CH], rE[CH];
        const float* xp = xphy + (size_t)g * 3;     // step 0
#pragma unroll
        for (int i = 0; i < CH; i++) {
            rP[i] = xp[0]; rT[i] = xp[1]; rE[i] = xp[2];
            xp += (size_t)G_CELLS * 3;
        }
        for (int k = 0; k < NCHUNK - 1; ++k) {       // chunks 0..71
            if (((k & 1) == 0) && k >= 4) {
                BAR_SYNC(3 + ((k >> 1) & 1));        // consumer freed super (k/2-2)
                flush_q(k - 4);
                flush_q(k - 3);
            }
            const int s = k & 3;
#pragma unroll
            for (int i = 0; i < CH; i++) {
                const float P = rP[i], Tm = rT[i], PE = rE[i];
                rP[i] = xp[0]; rT[i] = xp[1]; rE[i] = xp[2];
                xp += (size_t)G_CELLS * 3;
                const float inflow = snow_adv(P, Tm);
                buf[s][i][lane] = make_float2(inflow, PE);
            }
            if (k & 1) BAR_ARRIVE(1 + ((k >> 1) & 1));   // super-chunk full
        }
        {   // final chunk 72 (slot 0): no loads
            BAR_SYNC(3);                              // consumer freed super 34
            flush_q(68);
            flush_q(69);
#pragma unroll
            for (int i = 0; i < CH; i++) {
                const float inflow = snow_adv(rP[i], rT[i]);
                buf[0][i][lane] = make_float2(inflow, rE[i]);
            }
            BAR_ARRIVE(1);                            // "super 36" full
        }
        // Tail flushes as consumer finishes.
        BAR_SYNC(4);   // super 35 freed
        flush_q(70);
        flush_q(71);
        BAR_SYNC(3);   // super 36 (chunk 72) freed
        flush_q(72);
    } else {
        // ---- CONSUMER: SM/SUZ/SLZ chain (rotation deepened: e1 carried) ----
        const float BETA = phy[0], FC = phy[1], K0 = phy[2], K1 = phy[3];
        const float K2 = phy[4], LP = phy[5], PERCmax = phy[6], UZL = phy[7];
        const float BETAET = phy[12], C = phy[13];

        const float invFC = 1.0f / FC;
        const float clgA  = BETA   * lg2f_(invFC);
        const float clgB  = BETAET * lg2f_(1.0f / (LP * FC));
        const float oneK0 = 1.0f - K0;
        const float K0UZL = K0 * UZL;
        const float oneK1 = 1.0f - K1;

        float SM = 0.001f, SUZ = 0.001f, SLZ = 0.001f;
        float CSLZ = C * SLZ;
        float omcf = 1.0f - CSLZ * invFC;
        // Rotated carried value: e1 = min((SM/FC)^BETA, 1) for the NEXT step,
        // computed at each step's tail inside the lg2/ex2 shadows.
        float e1 = ex2f_(fminf(fmaf(BETA, lg2f_(SM), clgA), 0.0f));

        // 1-step-lookahead LDS ring (replaces the 20-reg v[CH] batch).
        float2 vcur;

        auto do_chunk = [&](int k, int knext, bool last) {
            const int s = k & 3;
#pragma unroll
            for (int i = 0; i < CH; i++) {
                const float inflow = vcur.x, PETt = vcur.y;
                // Prefetch next step's (inflow, PET): LDS issued at step start,
                // 29-cyc latency hidden inside this step's chain.
                if (i < CH - 1) {
                    vcur = buf[s][i + 1][lane];
                } else if (!last) {
                    vcur = buf[knext & 3][0][lane];
                }

                // --- chain: SM1 immediately (e1 already in flight) ---
                const float t1 = SM + inflow;
                const float SM1 = fmaf(-inflow, e1, t1);   // >= SM
                const float lg1 = lg2f_(SM1);
                // off-path in lg1 shadow:
                const float SM2 = fminf(SM1, FC);
                const float floor3 = fmaxf(SM2 - PETt, NEARZERO_F);
                const float d = t1 - SM2;                  // recharge + excess

                const float e2 = ex2f_(fmaf(BETAET, lg1, clgB));
                // off-path in e2 shadow (SUZ front half):
                const float SUZ1 = SUZ + d;
                const float PERC = fminf(SUZ1, PERCmax);
                const float SUZ2 = fmaxf(SUZ1 - PERCmax, 0.0f);
                const float SUZ3 = fminf(SUZ2, fmaf(oneK0, SUZ2, K0UZL));
                SUZ = oneK1 * SUZ3;
                const float Q01 = SUZ2 - SUZ;

                // --- chain tail ---
                const float SM3 = fmaxf(fmaf(-PETt, e2, SM2), floor3);
                const float SMn = fmaf(omcf, SM3, CSLZ);   // + capillary
                SM = SMn;
                const float lgn = lg2f_(SMn);              // rotated lg2
                // off-path tail in lgn shadow:
                const float cap = SMn - SM3;
                const float SLZ1 = fmaxf(SLZ - cap, NEARZERO_F) + PERC;
                const float Q2 = K2 * SLZ1;
                SLZ = SLZ1 - Q2;
                CSLZ = C * SLZ;
                omcf = fmaf(-CSLZ, invFC, 1.0f);
                qbuf[s][i][lane] = Q01 + Q2;
                // rotated head of next step (inside its own ex2 shadow):
                e1 = ex2f_(fminf(fmaf(BETA, lgn, clgA), 0.0f));
            }
        };

        // 36 full super-chunks (chunks 0..71), then final chunk 72.
        for (int j = 0; j < 36; ++j) {
            BAR_SYNC(1 + (j & 1));              // super full (acquire)
            if (j == 0) vcur = buf[0][0][lane]; // prime the LDS ring
            do_chunk(2 * j,     2 * j + 1, false);
            do_chunk(2 * j + 1, 2 * j + 2, (j == 35));  // j=35: next chunk 72
            BAR_ARRIVE(3 + (j & 1));            // super free + Q ready (release)
        }
        BAR_SYNC(1);                            // "super 36" full
        vcur = buf[0][0][lane];                 // chunk 72 lives in slot 0
        do_chunk(72, 0, true);
        BAR_ARRIVE(3);
    }
}

extern "C" void kernel_launch(void* const* d_in, const int* in_sizes, int n_in,
                              void* d_out, int out_size) {
    const float* xphy   = (const float*)d_in[0];   // 730*8000*3
    const float* params = (const float*)d_in[1];   // 730*8000*14
    float* out = (float*)d_out;                    // 730*8000

    hbv_kernel<<<125, 128>>>(xphy, params, out);   // 125 * 64 cells = 8000
}

// round 15
// speedup vs baseline: 1.0892x; 1.0329x over previous
#include <cuda_runtime.h>
#include <cstddef>

#define G_CELLS 8000
#define T_STEPS 730
#define CH 10              // steps per chunk; 730 = 10 * 73
#define NCHUNK 73
#define CPB 64             // cells per block; 8000 = 125 * 64
#define NEARZERO_F 1e-5f

__device__ __forceinline__ float ex2f_(float x) {
    float r; asm("ex2.approx.f32 %0, %1;" : "=f"(r) : "f"(x)); return r;
}
__device__ __forceinline__ float lg2f_(float x) {
    float r; asm("lg2.approx.f32 %0, %1;" : "=f"(r) : "f"(x)); return r;
}

// Named barriers at SUPER-CHUNK (2-chunk) granularity, 4-slot data ring.
// full: id 1+(j&1) (producer -> consumer), free: id 3+(j&1) (consumer -> producer).
// count = 128. bar.sync/arrive carry membar.cta-equivalent fence semantics.
#define BAR_SYNC(id)   asm volatile("bar.sync %0, 128;"   :: "r"(id) : "memory")
#define BAR_ARRIVE(id) asm volatile("bar.arrive %0, 128;" :: "r"(id) : "memory")

__global__ __launch_bounds__(128, 1) void hbv_kernel(
    const float* __restrict__ xphy,    // [730, 8000, 3] (P, T, PET)
    const float* __restrict__ params,  // [730, 8000, 14]
    float* __restrict__ out)           // [730, 8000]
{
    __shared__ float2 buf[4][CH][CPB];   // (inflow, PET) producer -> consumer
    __shared__ float  qbuf[4][CH][CPB];  // Q results    consumer -> producer

    const int tid  = threadIdx.x;
    const int lane = tid & 63;                 // cell slot within block
    const bool is_producer = (tid >= 64);
    const int g = blockIdx.x * CPB + lane;     // always < 8000

    // BETA, FC, K0, K1, K2, LP, PERCmax, UZL, TT, CFMAX, CFR, CWH, BETAET, C
    const float lo[14] = {1.0f, 50.0f, 0.05f, 0.01f, 0.001f, 0.2f, 0.0f,
                          0.0f, -2.5f, 0.5f, 0.0f, 0.0f, 0.3f, 0.0f};
    const float hi[14] = {6.0f, 1000.0f, 0.9f, 0.5f, 0.2f, 1.0f, 10.0f,
                          100.0f, 2.5f, 10.0f, 0.1f, 0.2f, 5.0f, 1.0f};

    const float* pr = params + ((size_t)(T_STEPS - 1) * G_CELLS + (size_t)g) * 14;
    float phy[14];
#pragma unroll
    for (int i = 0; i < 14; i++) {
        const float s = 1.0f / (1.0f + __expf(-pr[i]));
        phy[i] = fmaf(s, hi[i] - lo[i], lo[i]);
    }

    if (is_producer) {
        // -------- PRODUCER: snow recurrence + input loads + Q store-out --------
        const float TT = phy[8], CFMAX = phy[9], CWH = phy[11];
        const float CFRCF = phy[10] * phy[9];

        float SP = 0.001f, MW = 0.001f;

        auto snow_adv = [&](float P, float Tm) -> float {
            const bool  rain = (Tm >= TT);
            const float RAIN = rain ? P : 0.0f;
            const float SNOW = rain ? 0.0f : P;
            const float w    = (rain ? CFMAX : CFRCF) * (Tm - TT);
            const float SP1  = SP + SNOW;
            const float transfer = fminf(fmaxf(w, -MW), SP1);
            SP = SP1 - transfer;
            const float MW2 = MW + transfer;
            const float v   = fmaf(-CWH, SP, MW2);
            const float tosoil = fmaxf(v, 0.0f);
            MW = MW2 - tosoil;
            return RAIN + tosoil;
        };

        auto flush_q = [&](int m) {
            float* o = out + (size_t)(m * CH) * G_CELLS + g;
            const int s = m & 3;
#pragma unroll
            for (int i = 0; i < CH; i++) {
                o[(size_t)i * G_CELLS] = qbuf[s][i][lane];
            }
        };

        // Raw-input ring: next chunk's inputs, loaded one chunk early.
        float rP[CH], rT[CH], rE[CH];
        const float* xp = xphy + (size_t)g * 3;     // step 0
#pragma unroll
        for (int i = 0; i < CH; i++) {
            rP[i] = xp[0]; rT[i] = xp[1]; rE[i] = xp[2];
            xp += (size_t)G_CELLS * 3;
        }
        for (int k = 0; k < NCHUNK - 1; ++k) {       // chunks 0..71
            if (((k & 1) == 0) && k >= 4) {
                BAR_SYNC(3 + ((k >> 1) & 1));        // consumer freed super (k/2-2)
                flush_q(k - 4);
                flush_q(k - 3);
            }
            const int s = k & 3;
#pragma unroll
            for (int i = 0; i < CH; i++) {
                const float P = rP[i], Tm = rT[i], PE = rE[i];
                rP[i] = xp[0]; rT[i] = xp[1]; rE[i] = xp[2];
                xp += (size_t)G_CELLS * 3;
                const float inflow = snow_adv(P, Tm);
                buf[s][i][lane] = make_float2(inflow, PE);
            }
            if (k & 1) BAR_ARRIVE(1 + ((k >> 1) & 1));   // super-chunk full
        }
        {   // final chunk 72 (slot 0): no loads
            BAR_SYNC(3);                              // consumer freed super 34
            flush_q(68);
            flush_q(69);
#pragma unroll
            for (int i = 0; i < CH; i++) {
                const float inflow = snow_adv(rP[i], rT[i]);
                buf[0][i][lane] = make_float2(inflow, rE[i]);
            }
            BAR_ARRIVE(1);                            // "super 36" full
        }
        // Tail flushes as consumer finishes.
        BAR_SYNC(4);   // super 35 freed
        flush_q(70);
        flush_q(71);
        BAR_SYNC(3);   // super 36 (chunk 72) freed
        flush_q(72);
    } else {
        // ---- CONSUMER: SM chain with speculative dual-lg2 tail + FSEL ----
        const float BETA = phy[0], FC = phy[1], K0 = phy[2], K1 = phy[3];
        const float K2 = phy[4], LP = phy[5], PERCmax = phy[6], UZL = phy[7];
        const float BETAET = phy[12], C = phy[13];

        const float invFC = 1.0f / FC;
        const float clgA  = BETA   * lg2f_(invFC);
        const float clgB  = BETAET * lg2f_(1.0f / (LP * FC));
        const float oneK0 = 1.0f - K0;
        const float K0UZL = K0 * UZL;
        const float oneK1 = 1.0f - K1;

        float SM = 0.001f, SUZ = 0.001f, SLZ = 0.001f;
        float CSLZ = C * SLZ;
        float omcf = 1.0f - CSLZ * invFC;
        float lgSM = lg2f_(SM);                 // rotated loop-carried value

        auto do_chunk = [&](int k) {
            const int s = k & 3;
            float2 v[CH];
#pragma unroll
            for (int i = 0; i < CH; i++) v[i] = buf[s][i][lane];

#pragma unroll
            for (int i = 0; i < CH; i++) {
                const float inflow = v[i].x, PETt = v[i].y;

                // --- chain head (lgSM already computed last step) ---
                const float s1 = fminf(fmaf(BETA, lgSM, clgA), 0.0f);
                const float e1 = ex2f_(s1);
                // off-path in e1 shadow:
                const float t1 = SM + inflow;

                const float SM1 = fmaf(-inflow, e1, t1);   // >= SM
                const float lg1 = lg2f_(SM1);
                // off-path in lg1 shadow:
                const float SM2 = fminf(SM1, FC);
                const float floor3 = fmaxf(SM2 - PETt, NEARZERO_F);
                const float d = t1 - SM2;                  // recharge + excess
                // precompute the collapsed-tail constants (off-path):
                const float c1 = -omcf * PETt;             // -omcf*PET
                const float c2 = fmaf(omcf, SM2, CSLZ);    // omcf*SM2 + CSLZ
                const float SMn_f = fmaf(omcf, floor3, CSLZ);  // floor arm
                const float lg_f = lg2f_(SMn_f);           // speculative MUFU

                const float e2 = ex2f_(fmaf(BETAET, lg1, clgB));
                // off-path in e2 shadow (SUZ front half):
                const float SUZ1 = SUZ + d;
                const float SUZ2 = fmaxf(SUZ1 - PERCmax, 0.0f);
                const float PERC = SUZ1 - SUZ2;            // == min(SUZ1,PERCmax)
                const float SUZ3 = fminf(SUZ2, fmaf(oneK0, SUZ2, K0UZL));
                SUZ = oneK1 * SUZ3;
                const float Q01 = SUZ2 - SUZ;

                // --- chain tail: ONE fma from e2, then lg2, then FSEL ---
                const float SMn_x = fmaf(c1, e2, c2);      // omcf*x + CSLZ
                const float lg_x = lg2f_(SMn_x);           // CHAIN MUFU
                // predicate + both selects resolve off-path in parallel:
                const float x = fmaf(-PETt, e2, SM2);
                const bool  px = (x >= floor3);
                const float SM3 = px ? x : floor3;
                const float SMn = px ? SMn_x : SMn_f;
                SM = SMn;
                lgSM = px ? lg_x : lg_f;                   // CHAIN FSEL (4 cyc)

                // off-path tail in next-e1's shadow:
                const float cap = SMn - SM3;
                const float SLZ1 = fmaxf(SLZ - cap, NEARZERO_F) + PERC;
                const float Q2 = K2 * SLZ1;
                SLZ = SLZ1 - Q2;
                CSLZ = C * SLZ;
                omcf = fmaf(-CSLZ, invFC, 1.0f);
                qbuf[s][i][lane] = Q01 + Q2;
            }
        };

        // 36 full super-chunks (chunks 0..71), then final chunk 72.
        for (int j = 0; j < 36; ++j) {
            BAR_SYNC(1 + (j & 1));              // super full (acquire)
            do_chunk(2 * j);
            do_chunk(2 * j + 1);
            BAR_ARRIVE(3 + (j & 1));            // super free + Q ready (release)
        }
        BAR_SYNC(1);                            // "super 36" full
        do_chunk(72);
        BAR_ARRIVE(3);
    }
}

extern "C" void kernel_launch(void* const* d_in, const int* in_sizes, int n_in,
                              void* d_out, int out_size) {
    const float* xphy   = (const float*)d_in[0];   // 730*8000*3
    const float* params = (const float*)d_in[1];   // 730*8000*14
    float* out = (float*)d_out;                    // 730*8000

    hbv_kernel<<<125, 128>>>(xphy, params, out);   // 125 * 64 cells = 8000
}